// round 1
// baseline (speedup 1.0000x reference)
#include <cuda_runtime.h>
#include <cuda_bf16.h>
#include <cstdint>

// Problem constants (fixed benchmark shapes)
constexpr int Bn = 4;
constexpr int Sn = 4096;
constexpr int Dn = 256;

// Scratch (device globals — no cudaMalloc allowed)
__device__ float g_V[Bn * Sn * Dn];   // v = x @ W^T + b   (fp32, 16 MB)
__device__ float g_Sq[Bn * Sn];       // per-row sum of squares

// ---------------------------------------------------------------------------
// K1: per-row sum of squares (fp32). One warp per row.
// ---------------------------------------------------------------------------
__global__ void k_sq(const float* __restrict__ x) {
    int row  = blockIdx.x * 8 + (threadIdx.x >> 5);
    int lane = threadIdx.x & 31;
    const float* p = x + (size_t)row * Dn;
    float a = 0.f;
#pragma unroll
    for (int k = 0; k < 8; ++k) {
        float v = p[lane + 32 * k];
        a = fmaf(v, v, a);
    }
#pragma unroll
    for (int o = 16; o > 0; o >>= 1) a += __shfl_xor_sync(0xffffffffu, a, o);
    if (lane == 0) g_Sq[row] = a;
}

// ---------------------------------------------------------------------------
// K2: V = x @ W^T + b  (fp32 FFMA, smem-tiled).  CTA = 64 rows x 64 cols.
// ---------------------------------------------------------------------------
__global__ __launch_bounds__(256) void k_v(const float* __restrict__ x,
                                           const float* __restrict__ W,
                                           const float* __restrict__ bv) {
    __shared__ float xsm[64][33];
    __shared__ float wsm[64][33];
    int tid = threadIdx.x;
    int r0 = blockIdx.x * 64;
    int c0 = blockIdx.y * 64;
    int ty = tid >> 4, tx = tid & 15;

    float acc[4][4] = {};

    for (int kc = 0; kc < Dn; kc += 32) {
#pragma unroll
        for (int rep = 0; rep < 2; ++rep) {
            int uu = tid + rep * 256;          // 512 float4 units total
            int r = uu >> 3, cg = uu & 7;
            float4 gx = *reinterpret_cast<const float4*>(x + (size_t)(r0 + r) * Dn + kc + cg * 4);
            xsm[r][cg * 4 + 0] = gx.x; xsm[r][cg * 4 + 1] = gx.y;
            xsm[r][cg * 4 + 2] = gx.z; xsm[r][cg * 4 + 3] = gx.w;
            float4 gw = *reinterpret_cast<const float4*>(W + (size_t)(c0 + r) * Dn + kc + cg * 4);
            wsm[r][cg * 4 + 0] = gw.x; wsm[r][cg * 4 + 1] = gw.y;
            wsm[r][cg * 4 + 2] = gw.z; wsm[r][cg * 4 + 3] = gw.w;
        }
        __syncthreads();
#pragma unroll 8
        for (int kk = 0; kk < 32; ++kk) {
            float a[4], b[4];
#pragma unroll
            for (int i = 0; i < 4; ++i) a[i] = xsm[ty * 4 + i][kk];
#pragma unroll
            for (int j = 0; j < 4; ++j) b[j] = wsm[tx * 4 + j][kk];
#pragma unroll
            for (int i = 0; i < 4; ++i)
#pragma unroll
                for (int j = 0; j < 4; ++j)
                    acc[i][j] = fmaf(a[i], b[j], acc[i][j]);
        }
        __syncthreads();
    }
#pragma unroll
    for (int i = 0; i < 4; ++i)
#pragma unroll
        for (int j = 0; j < 4; ++j) {
            int r = r0 + ty * 4 + i;
            int c = c0 + tx * 4 + j;
            g_V[(size_t)r * Dn + c] = acc[i][j] + bv[c];
        }
}

// ---------------------------------------------------------------------------
// K3: fused  K = cauchy(d2)  ->  out = (K_offdiag @ V + v_s) / (rowsum + 1)
//
// Grid (32 s-tiles, 4 batches), 512 threads.  BM=128 s-rows, BN=64 t-cols.
// bf16 smem tiles (precision-safe off-diagonal; diagonal handled exactly
// via fp32 V re-add in the epilogue).
// ---------------------------------------------------------------------------
// smem byte offsets
constexpr int OFF_XS  = 0;            // bf16 [128][256]
constexpr int OFF_XTT = 65536;        // bf16 [256][68]  (x_t transposed, padded)
constexpr int OFF_VT  = 100352;       // bf16 [64][256]
constexpr int OFF_KT  = 133120;       // f32  [128][65]
constexpr int OFF_SQS = 166400;       // f32  [128]
constexpr int OFF_SQT = 166912;       // f32  [64]
constexpr int SMEM_BYTES = 167168;

__device__ __forceinline__ float2 bf2f(uint32_t u) {
    __nv_bfloat162 h = *reinterpret_cast<__nv_bfloat162*>(&u);
    return __bfloat1622float2(h);
}

__global__ __launch_bounds__(512, 1) void k_fused(const float* __restrict__ x,
                                                  const float* __restrict__ logt,
                                                  float* __restrict__ out) {
    extern __shared__ char smem[];
    __nv_bfloat16* s_xs  = reinterpret_cast<__nv_bfloat16*>(smem + OFF_XS);
    __nv_bfloat16* s_xtT = reinterpret_cast<__nv_bfloat16*>(smem + OFF_XTT);
    __nv_bfloat16* s_vt  = reinterpret_cast<__nv_bfloat16*>(smem + OFF_VT);
    float* s_kt  = reinterpret_cast<float*>(smem + OFF_KT);
    float* s_sqs = reinterpret_cast<float*>(smem + OFF_SQS);
    float* s_sqt = reinterpret_cast<float*>(smem + OFF_SQT);

    const int tid = threadIdx.x;
    const int bz  = blockIdx.y;                 // batch
    const int s0  = blockIdx.x * 128;
    const size_t base = (size_t)bz * Sn * Dn;

    const int ty = tid >> 4;   // 0..31  -> 4 rows each
    const int tx = tid & 15;   // 0..15  -> 4 gram cols / 16 acc cols

    // temperature
    float temp = fmaxf(expf(logt[0]), 1e-5f);
    const float invT2 = __fdividef(1.f, temp * temp);

    // ---- load x_s tile (bf16) + sq_s ----
    for (int u = tid; u < 8192; u += 512) {            // 128 rows * 64 float4
        int r = u >> 6, dg = u & 63;
        float4 g = *reinterpret_cast<const float4*>(x + base + (size_t)(s0 + r) * Dn + dg * 4);
        __nv_bfloat162* dst = reinterpret_cast<__nv_bfloat162*>(s_xs + r * Dn + dg * 4);
        dst[0] = __floats2bfloat162_rn(g.x, g.y);
        dst[1] = __floats2bfloat162_rn(g.z, g.w);
    }
    if (tid < 128) s_sqs[tid] = g_Sq[bz * Sn + s0 + tid];

    float acc[4][16];
#pragma unroll
    for (int i = 0; i < 4; ++i)
#pragma unroll
        for (int c = 0; c < 16; ++c) acc[i][c] = 0.f;
    float rsum[4] = {0.f, 0.f, 0.f, 0.f};

    for (int jt = 0; jt < 64; ++jt) {
        const int t0 = jt * 64;
        __syncthreads();

        // ---- load x_t (transposed) and v_t tiles ----
        for (int u = tid; u < 4096; u += 512) {        // 64 rows * 64 float4
            int t = u >> 6, dg = u & 63;
            float4 g = *reinterpret_cast<const float4*>(x + base + (size_t)(t0 + t) * Dn + dg * 4);
            int d = dg * 4;
            s_xtT[(d + 0) * 68 + t] = __float2bfloat16(g.x);
            s_xtT[(d + 1) * 68 + t] = __float2bfloat16(g.y);
            s_xtT[(d + 2) * 68 + t] = __float2bfloat16(g.z);
            s_xtT[(d + 3) * 68 + t] = __float2bfloat16(g.w);
        }
        for (int u = tid; u < 4096; u += 512) {
            int t = u >> 6, dg = u & 63;
            float4 g = *reinterpret_cast<const float4*>(g_V + base + (size_t)(t0 + t) * Dn + dg * 4);
            __nv_bfloat162* dst = reinterpret_cast<__nv_bfloat162*>(s_vt + t * Dn + dg * 4);
            dst[0] = __floats2bfloat162_rn(g.x, g.y);
            dst[1] = __floats2bfloat162_rn(g.z, g.w);
        }
        if (tid < 64) s_sqt[tid] = g_Sq[bz * Sn + t0 + tid];
        __syncthreads();

        // ---- phase 1: 128x64 Gram tile -> Cauchy kernel values ----
        {
            float dot[4][4];
#pragma unroll
            for (int i = 0; i < 4; ++i)
#pragma unroll
                for (int j = 0; j < 4; ++j) dot[i][j] = 0.f;

            const uint32_t* xsu = reinterpret_cast<const uint32_t*>(s_xs);
#pragma unroll 4
            for (int p = 0; p < 128; ++p) {
                float2 a[4];
#pragma unroll
                for (int i = 0; i < 4; ++i)
                    a[i] = bf2f(xsu[(ty * 4 + i) * 128 + p]);
                uint2 u0 = *reinterpret_cast<const uint2*>(s_xtT + (2 * p) * 68 + tx * 4);
                uint2 u1 = *reinterpret_cast<const uint2*>(s_xtT + (2 * p + 1) * 68 + tx * 4);
                float2 f00 = bf2f(u0.x), f01 = bf2f(u0.y);
                float2 f10 = bf2f(u1.x), f11 = bf2f(u1.y);
                float b0[4] = {f00.x, f00.y, f01.x, f01.y};
                float b1[4] = {f10.x, f10.y, f11.x, f11.y};
#pragma unroll
                for (int i = 0; i < 4; ++i)
#pragma unroll
                    for (int j = 0; j < 4; ++j) {
                        dot[i][j] = fmaf(a[i].x, b0[j], dot[i][j]);
                        dot[i][j] = fmaf(a[i].y, b1[j], dot[i][j]);
                    }
            }
#pragma unroll
            for (int i = 0; i < 4; ++i) {
                int r = ty * 4 + i;
#pragma unroll
                for (int j = 0; j < 4; ++j) {
                    int c = tx * 4 + j;
                    float d2 = s_sqs[r] + s_sqt[c] - 2.f * dot[i][j];
                    d2 = fmaxf(d2, 0.f);
                    float kv = __fdividef(1.f, fmaf(d2, invT2, 1.f));
                    if (s0 + r == t0 + c) kv = 0.f;   // diagonal excluded (added exactly later)
                    s_kt[r * 65 + c] = kv;
                }
            }
        }
        __syncthreads();

        // ---- phase 2: acc += K_tile @ V_tile ; rowsum ----
#pragma unroll 2
        for (int j = 0; j < 64; ++j) {
            float k4[4];
#pragma unroll
            for (int i = 0; i < 4; ++i) {
                k4[i] = s_kt[(ty * 4 + i) * 65 + j];
                rsum[i] += k4[i];
            }
            const uint4* vrow = reinterpret_cast<const uint4*>(s_vt + j * Dn);
            uint4 v0 = vrow[tx * 2], v1 = vrow[tx * 2 + 1];
            float vv[16];
            {
                float2 f;
                f = bf2f(v0.x); vv[0] = f.x; vv[1] = f.y;
                f = bf2f(v0.y); vv[2] = f.x; vv[3] = f.y;
                f = bf2f(v0.z); vv[4] = f.x; vv[5] = f.y;
                f = bf2f(v0.w); vv[6] = f.x; vv[7] = f.y;
                f = bf2f(v1.x); vv[8] = f.x; vv[9] = f.y;
                f = bf2f(v1.y); vv[10] = f.x; vv[11] = f.y;
                f = bf2f(v1.z); vv[12] = f.x; vv[13] = f.y;
                f = bf2f(v1.w); vv[14] = f.x; vv[15] = f.y;
            }
#pragma unroll
            for (int i = 0; i < 4; ++i)
#pragma unroll
                for (int c = 0; c < 16; ++c)
                    acc[i][c] = fmaf(k4[i], vv[c], acc[i][c]);
        }
    }

    // ---- epilogue: add exact fp32 diagonal contribution, normalize ----
#pragma unroll
    for (int i = 0; i < 4; ++i) {
        int r = ty * 4 + i;
        size_t rowo = base + (size_t)(s0 + r) * Dn;
        float inv = __fdividef(1.f, rsum[i] + 1.f);   // +1 = diagonal kernel value
#pragma unroll
        for (int cg = 0; cg < 4; ++cg) {
            int c = tx * 16 + cg * 4;
            float4 vv = *reinterpret_cast<const float4*>(g_V + rowo + c);
            float4 o;
            o.x = (acc[i][cg * 4 + 0] + vv.x) * inv;
            o.y = (acc[i][cg * 4 + 1] + vv.y) * inv;
            o.z = (acc[i][cg * 4 + 2] + vv.z) * inv;
            o.w = (acc[i][cg * 4 + 3] + vv.w) * inv;
            *reinterpret_cast<float4*>(out + rowo + c) = o;
        }
    }
}

// ---------------------------------------------------------------------------
extern "C" void kernel_launch(void* const* d_in, const int* in_sizes, int n_in,
                              void* d_out, int out_size) {
    const float* x    = (const float*)d_in[0];
    const float* W    = (const float*)d_in[1];
    const float* bv   = (const float*)d_in[2];
    const float* logt = (const float*)d_in[3];
    float* out = (float*)d_out;

    cudaFuncSetAttribute(k_fused, cudaFuncAttributeMaxDynamicSharedMemorySize, SMEM_BYTES);

    k_sq<<<(Bn * Sn) / 8, 256>>>(x);
    k_v<<<dim3((Bn * Sn) / 64, Dn / 64), 256>>>(x, W, bv);
    k_fused<<<dim3(Sn / 128, Bn), 512, SMEM_BYTES>>>(x, logt, out);
}

// round 6
// speedup vs baseline: 12.6611x; 12.6611x over previous
#include <cuda_runtime.h>
#include <cuda_bf16.h>
#include <cstdint>

constexpr int Bn = 4;
constexpr int Sn = 4096;
constexpr int Dn = 256;

// Device-global scratch (no cudaMalloc allowed)
__device__ float         g_V [(size_t)Bn * Sn * Dn];   // v = xW^T+b, fp32 (epilogue/diag)
__device__ float         g_Sq[(size_t)Bn * Sn];        // per-row ||x||^2 fp32
__device__ __nv_bfloat16 g_Xb[(size_t)Bn * Sn * Dn];   // x in bf16
__device__ __nv_bfloat16 g_Vt[(size_t)Bn * Dn * Sn];   // V transposed [B][D][S] bf16

// ============================ helpers ============================
__device__ __forceinline__ uint32_t smem_u32(const void* p) {
    uint32_t a;
    asm("{ .reg .u64 t; cvta.to.shared.u64 t, %1; cvt.u32.u64 %0, t; }" : "=r"(a) : "l"(p));
    return a;
}
__device__ __forceinline__ void ldsm_x4(uint32_t* r, uint32_t addr) {
    asm volatile("ldmatrix.sync.aligned.m8n8.x4.shared.b16 {%0,%1,%2,%3}, [%4];"
                 : "=r"(r[0]), "=r"(r[1]), "=r"(r[2]), "=r"(r[3]) : "r"(addr));
}
__device__ __forceinline__ void mma16816(float* d, const uint32_t* a, const uint32_t* b) {
    asm volatile("mma.sync.aligned.m16n8k16.row.col.f32.bf16.bf16.f32 "
                 "{%0,%1,%2,%3}, {%4,%5,%6,%7}, {%8,%9}, {%0,%1,%2,%3};"
                 : "+f"(d[0]), "+f"(d[1]), "+f"(d[2]), "+f"(d[3])
                 : "r"(a[0]), "r"(a[1]), "r"(a[2]), "r"(a[3]), "r"(b[0]), "r"(b[1]));
}

// ============================ K1: x->bf16 + ||x||^2 ============================
__global__ void k_prep(const float* __restrict__ x) {
    int row  = blockIdx.x * 8 + (threadIdx.x >> 5);
    int lane = threadIdx.x & 31;
    const float4* p = reinterpret_cast<const float4*>(x + (size_t)row * Dn) + lane * 2;
    float4 a = p[0], b = p[1];
    float s = 0.f;
    s = fmaf(a.x, a.x, s); s = fmaf(a.y, a.y, s); s = fmaf(a.z, a.z, s); s = fmaf(a.w, a.w, s);
    s = fmaf(b.x, b.x, s); s = fmaf(b.y, b.y, s); s = fmaf(b.z, b.z, s); s = fmaf(b.w, b.w, s);
    uint4 o;
    { __nv_bfloat162 h = __floats2bfloat162_rn(a.x, a.y); o.x = *reinterpret_cast<uint32_t*>(&h); }
    { __nv_bfloat162 h = __floats2bfloat162_rn(a.z, a.w); o.y = *reinterpret_cast<uint32_t*>(&h); }
    { __nv_bfloat162 h = __floats2bfloat162_rn(b.x, b.y); o.z = *reinterpret_cast<uint32_t*>(&h); }
    { __nv_bfloat162 h = __floats2bfloat162_rn(b.z, b.w); o.w = *reinterpret_cast<uint32_t*>(&h); }
    *reinterpret_cast<uint4*>(g_Xb + (size_t)row * Dn + lane * 8) = o;
#pragma unroll
    for (int of = 16; of > 0; of >>= 1) s += __shfl_xor_sync(0xffffffffu, s, of);
    if (lane == 0) g_Sq[row] = s;
}

// ============================ K2: V = xW^T + b (fp32 + bf16-transposed out) ====
__global__ __launch_bounds__(256) void k_v(const float* __restrict__ x,
                                           const float* __restrict__ W,
                                           const float* __restrict__ bv) {
    __shared__ float xsm[64][33];
    __shared__ float wsm[64][33];
    __shared__ float s_t[64][65];
    int tid = threadIdx.x;
    int r0 = blockIdx.x * 64;
    int c0 = blockIdx.y * 64;
    int ty = tid >> 4, tx = tid & 15;

    float acc[4][4] = {};
    for (int kc = 0; kc < Dn; kc += 32) {
#pragma unroll
        for (int rep = 0; rep < 2; ++rep) {
            int uu = tid + rep * 256;
            int r = uu >> 3, cg = uu & 7;
            float4 gx = *reinterpret_cast<const float4*>(x + (size_t)(r0 + r) * Dn + kc + cg * 4);
            xsm[r][cg * 4 + 0] = gx.x; xsm[r][cg * 4 + 1] = gx.y;
            xsm[r][cg * 4 + 2] = gx.z; xsm[r][cg * 4 + 3] = gx.w;
            float4 gw = *reinterpret_cast<const float4*>(W + (size_t)(c0 + r) * Dn + kc + cg * 4);
            wsm[r][cg * 4 + 0] = gw.x; wsm[r][cg * 4 + 1] = gw.y;
            wsm[r][cg * 4 + 2] = gw.z; wsm[r][cg * 4 + 3] = gw.w;
        }
        __syncthreads();
#pragma unroll 8
        for (int kk = 0; kk < 32; ++kk) {
            float a[4], b[4];
#pragma unroll
            for (int i = 0; i < 4; ++i) a[i] = xsm[ty * 4 + i][kk];
#pragma unroll
            for (int j = 0; j < 4; ++j) b[j] = wsm[tx * 4 + j][kk];
#pragma unroll
            for (int i = 0; i < 4; ++i)
#pragma unroll
                for (int j = 0; j < 4; ++j) acc[i][j] = fmaf(a[i], b[j], acc[i][j]);
        }
        __syncthreads();
    }
#pragma unroll
    for (int i = 0; i < 4; ++i)
#pragma unroll
        for (int j = 0; j < 4; ++j) {
            int r = ty * 4 + i, c = tx * 4 + j;
            float v = acc[i][j] + bv[c0 + c];
            g_V[(size_t)(r0 + r) * Dn + c0 + c] = v;
            s_t[c][r] = v;
        }
    __syncthreads();
    int b   = r0 >> 12;
    int s0l = r0 & (Sn - 1);
    int d   = tid >> 2;
    int sg  = (tid & 3) * 16;
#pragma unroll
    for (int q = 0; q < 2; ++q) {
        uint4 o;
        float* sp = &s_t[d][sg + q * 8];
        { __nv_bfloat162 h = __floats2bfloat162_rn(sp[0], sp[1]); o.x = *reinterpret_cast<uint32_t*>(&h); }
        { __nv_bfloat162 h = __floats2bfloat162_rn(sp[2], sp[3]); o.y = *reinterpret_cast<uint32_t*>(&h); }
        { __nv_bfloat162 h = __floats2bfloat162_rn(sp[4], sp[5]); o.z = *reinterpret_cast<uint32_t*>(&h); }
        { __nv_bfloat162 h = __floats2bfloat162_rn(sp[6], sp[7]); o.w = *reinterpret_cast<uint32_t*>(&h); }
        *reinterpret_cast<uint4*>(g_Vt + ((size_t)b * Dn + (c0 + d)) * Sn + s0l + sg + q * 8) = o;
    }
}

// ============================ K3: fused HMMA main kernel ====================
// smem layout (dynamic). Row strides chosen so stride mod 128B == 16B
// (4 banks) -> conflict-free 8-row ldmatrix groups.
constexpr int XS_STR = 264;   // elements per row (128 rows)
constexpr int XT_STR = 264;   // (64 rows)
constexpr int VT_STR = 72;    // (256 rows)
constexpr int P_STR  = 72;    // (128 rows)

constexpr int OFF_SQ = 0;                         // 4096 f32 = 16384
constexpr int OFF_RS = 16384;                     // 128 f32 = 512
constexpr int OFF_XS = 16896;                     // 128*264*2 = 67584
constexpr int OFF_XT = OFF_XS + 128 * XS_STR * 2; // 84480
constexpr int OFF_VT = OFF_XT + 64 * XT_STR * 2;  // 118272
constexpr int OFF_P  = OFF_VT + 256 * VT_STR * 2; // 155136
constexpr int SMEM_MAIN = OFF_P + 128 * P_STR * 2; // 173568

__global__ __launch_bounds__(512, 1) void k_main(const float* __restrict__ logt,
                                                 float* __restrict__ out) {
    extern __shared__ char smem[];
    const uint32_t sb = smem_u32(smem);
    float* s_sq = reinterpret_cast<float*>(smem + OFF_SQ);
    float* s_rs = reinterpret_cast<float*>(smem + OFF_RS);

    const int tid  = threadIdx.x;
    const int w    = tid >> 5;
    const int lane = tid & 31;
    const int lq   = lane >> 2;     // 0..7
    const int lr   = lane & 3;      // 0..3

    const int bz = blockIdx.y;
    const int s0 = blockIdx.x * 128;
    const size_t base = (size_t)bz * Sn * Dn;

    // phase-1 warp tile: 16 (m) x 32 (n); warps 8 x 2
    const int wm = w >> 1, wn = w & 1;
    const int m0 = wm * 16, n0 = wn * 32;
    // phase-2 warp tile: 32 (m) x 64 (n); warps 4 x 4
    const int wm2 = w >> 2, wn2 = w & 3;
    const int m0b = wm2 * 32, n0b = wn2 * 64;

    // ---- initial loads ----
    {
        const float4* q = reinterpret_cast<const float4*>(g_Sq + (size_t)bz * Sn);
        for (int u = tid; u < 1024; u += 512) reinterpret_cast<float4*>(s_sq)[u] = q[u];
    }
    if (tid < 128) s_rs[tid] = 0.f;
    for (int u = tid; u < 4096; u += 512) {
        int r = u >> 5, cg = u & 31;
        uint4 g = *reinterpret_cast<const uint4*>(g_Xb + base + (size_t)(s0 + r) * Dn + cg * 8);
        *reinterpret_cast<uint4*>(smem + OFF_XS + (r * XS_STR + cg * 8) * 2) = g;
    }

    const float temp  = fmaxf(expf(logt[0]), 1e-5f);
    const float invT2 = __fdividef(1.f, temp * temp);

    // ldmatrix per-lane base addresses
    const uint32_t aA  = sb + OFF_XS + (((m0 + (lane & 15)) * XS_STR + ((lane >> 4) << 3)) << 1);
    const uint32_t aB0 = sb + OFF_XT + (((n0 + ((lane >> 4) << 3) + (lane & 7)) * XT_STR
                                         + (((lane >> 3) & 1) << 3)) << 1);
    const uint32_t aB1 = aB0 + 16 * XT_STR * 2;
    const uint32_t aP0 = sb + OFF_P + (((m0b + (lane & 15)) * P_STR + ((lane >> 4) << 3)) << 1);
    const uint32_t aP1 = aP0 + 16 * P_STR * 2;
    uint32_t aV[4];
#pragma unroll
    for (int bq = 0; bq < 4; ++bq)
        aV[bq] = sb + OFF_VT + (((n0b + bq * 16 + ((lane >> 4) << 3) + (lane & 7)) * VT_STR
                                 + (((lane >> 3) & 1) << 3)) << 1);

    const int ra = m0 + lq, rb = ra + 8;   // phase-1 rows owned by this lane

    float dacc[2][8][4];
#pragma unroll
    for (int a = 0; a < 2; ++a)
#pragma unroll
        for (int b = 0; b < 8; ++b)
#pragma unroll
            for (int c = 0; c < 4; ++c) dacc[a][b][c] = 0.f;
    float rsA = 0.f, rsB = 0.f;

    __syncthreads();
    const float sqA = s_sq[s0 + ra];
    const float sqB = s_sq[s0 + rb];

    for (int jt = 0; jt < 64; ++jt) {
        const int t0 = jt * 64;
        __syncthreads();   // previous phase-2 done reading Xt/Vt/P

        // ---- load Xt [64][256] and Vt [256][64] ----
#pragma unroll
        for (int k = 0; k < 4; ++k) {
            int u = tid + k * 512;
            int r = u >> 5, cg = u & 31;
            uint4 g = *reinterpret_cast<const uint4*>(g_Xb + base + (size_t)(t0 + r) * Dn + cg * 8);
            *reinterpret_cast<uint4*>(smem + OFF_XT + (r * XT_STR + cg * 8) * 2) = g;
        }
#pragma unroll
        for (int k = 0; k < 4; ++k) {
            int u = tid + k * 512;
            int r = u >> 3, cg = u & 7;
            uint4 g = *reinterpret_cast<const uint4*>(g_Vt + ((size_t)bz * Dn + r) * Sn + t0 + cg * 8);
            *reinterpret_cast<uint4*>(smem + OFF_VT + (r * VT_STR + cg * 8) * 2) = g;
        }
        __syncthreads();

        // ---- phase 1: S = Xs @ Xt^T  (16x32 per warp, K=256) ----
        float sacc[4][4];
#pragma unroll
        for (int f = 0; f < 4; ++f)
#pragma unroll
            for (int c = 0; c < 4; ++c) sacc[f][c] = 0.f;
        {
            uint32_t pa = aA, pb0 = aB0, pb1 = aB1;
#pragma unroll
            for (int ks = 0; ks < 16; ++ks) {
                uint32_t A[4], B0[4], B1[4];
                ldsm_x4(A, pa);
                ldsm_x4(B0, pb0);
                ldsm_x4(B1, pb1);
                mma16816(sacc[0], A, B0);
                mma16816(sacc[1], A, B0 + 2);
                mma16816(sacc[2], A, B1);
                mma16816(sacc[3], A, B1 + 2);
                pa += 32; pb0 += 32; pb1 += 32;
            }
        }

        // ---- elementwise: Cauchy, diag-zero, rowsum, bf16 pack -> P ----
#pragma unroll
        for (int fn = 0; fn < 4; ++fn) {
            const int c = n0 + fn * 8 + 2 * lr;
            const float sqt0 = s_sq[t0 + c];
            const float sqt1 = s_sq[t0 + c + 1];
            float d00 = fmaxf(sqA + sqt0 - 2.f * sacc[fn][0], 0.f);
            float d01 = fmaxf(sqA + sqt1 - 2.f * sacc[fn][1], 0.f);
            float d10 = fmaxf(sqB + sqt0 - 2.f * sacc[fn][2], 0.f);
            float d11 = fmaxf(sqB + sqt1 - 2.f * sacc[fn][3], 0.f);
            float k00 = __fdividef(1.f, fmaf(d00, invT2, 1.f));
            float k01 = __fdividef(1.f, fmaf(d01, invT2, 1.f));
            float k10 = __fdividef(1.f, fmaf(d10, invT2, 1.f));
            float k11 = __fdividef(1.f, fmaf(d11, invT2, 1.f));
            if (s0 + ra == t0 + c)     k00 = 0.f;
            if (s0 + ra == t0 + c + 1) k01 = 0.f;
            if (s0 + rb == t0 + c)     k10 = 0.f;
            if (s0 + rb == t0 + c + 1) k11 = 0.f;
            rsA += k00 + k01;
            rsB += k10 + k11;
            __nv_bfloat162 hA = __floats2bfloat162_rn(k00, k01);
            __nv_bfloat162 hB = __floats2bfloat162_rn(k10, k11);
            *reinterpret_cast<uint32_t*>(smem + OFF_P + (ra * P_STR + c) * 2) =
                *reinterpret_cast<uint32_t*>(&hA);
            *reinterpret_cast<uint32_t*>(smem + OFF_P + (rb * P_STR + c) * 2) =
                *reinterpret_cast<uint32_t*>(&hB);
        }
        __syncthreads();

        // ---- phase 2: D += P @ Vt^T  (32x64 per warp, K=64) ----
        {
            uint32_t qa0 = aP0, qa1 = aP1;
            uint32_t qv0 = aV[0], qv1 = aV[1], qv2 = aV[2], qv3 = aV[3];
#pragma unroll
            for (int ks = 0; ks < 4; ++ks) {
                uint32_t A0[4], A1[4], Bv0[4], Bv1[4], Bv2[4], Bv3[4];
                ldsm_x4(A0, qa0);
                ldsm_x4(A1, qa1);
                ldsm_x4(Bv0, qv0);
                ldsm_x4(Bv1, qv1);
                ldsm_x4(Bv2, qv2);
                ldsm_x4(Bv3, qv3);
                mma16816(dacc[0][0], A0, Bv0);     mma16816(dacc[1][0], A1, Bv0);
                mma16816(dacc[0][1], A0, Bv0 + 2); mma16816(dacc[1][1], A1, Bv0 + 2);
                mma16816(dacc[0][2], A0, Bv1);     mma16816(dacc[1][2], A1, Bv1);
                mma16816(dacc[0][3], A0, Bv1 + 2); mma16816(dacc[1][3], A1, Bv1 + 2);
                mma16816(dacc[0][4], A0, Bv2);     mma16816(dacc[1][4], A1, Bv2);
                mma16816(dacc[0][5], A0, Bv2 + 2); mma16816(dacc[1][5], A1, Bv2 + 2);
                mma16816(dacc[0][6], A0, Bv3);     mma16816(dacc[1][6], A1, Bv3);
                mma16816(dacc[0][7], A0, Bv3 + 2); mma16816(dacc[1][7], A1, Bv3 + 2);
                qa0 += 32; qa1 += 32; qv0 += 32; qv1 += 32; qv2 += 32; qv3 += 32;
            }
        }
    }

    // ---- rowsum reduce ----
    __syncthreads();
    atomicAdd(&s_rs[ra], rsA);
    atomicAdd(&s_rs[rb], rsB);
    __syncthreads();

    // ---- epilogue: out = (D + v_row) / (rowsum + 1) ----
#pragma unroll
    for (int mi = 0; mi < 2; ++mi) {
        const int r0e = m0b + mi * 16 + lq;
        const int r1e = r0e + 8;
        const float invA = __fdividef(1.f, s_rs[r0e] + 1.f);
        const float invB = __fdividef(1.f, s_rs[r1e] + 1.f);
        const size_t go0 = ((size_t)bz * Sn + s0 + r0e) * Dn;
        const size_t go1 = ((size_t)bz * Sn + s0 + r1e) * Dn;
#pragma unroll
        for (int fn = 0; fn < 8; ++fn) {
            const int c = n0b + fn * 8 + 2 * lr;
            float2 v0 = *reinterpret_cast<const float2*>(g_V + go0 + c);
            float2 v1 = *reinterpret_cast<const float2*>(g_V + go1 + c);
            float2 o0, o1;
            o0.x = (dacc[mi][fn][0] + v0.x) * invA;
            o0.y = (dacc[mi][fn][1] + v0.y) * invA;
            o1.x = (dacc[mi][fn][2] + v1.x) * invB;
            o1.y = (dacc[mi][fn][3] + v1.y) * invB;
            *reinterpret_cast<float2*>(out + go0 + c) = o0;
            *reinterpret_cast<float2*>(out + go1 + c) = o1;
        }
    }
}

// ============================ launch ============================
extern "C" void kernel_launch(void* const* d_in, const int* in_sizes, int n_in,
                              void* d_out, int out_size) {
    const float* x    = (const float*)d_in[0];
    const float* W    = (const float*)d_in[1];
    const float* bv   = (const float*)d_in[2];
    const float* logt = (const float*)d_in[3];
    float* out = (float*)d_out;

    cudaFuncSetAttribute(k_main, cudaFuncAttributeMaxDynamicSharedMemorySize, SMEM_MAIN);

    k_prep<<<(Bn * Sn) / 8, 256>>>(x);
    k_v<<<dim3((Bn * Sn) / 64, Dn / 64), 256>>>(x, W, bv);
    k_main<<<dim3(Sn / 128, Bn), 512, SMEM_MAIN>>>(logt, out);
}

// round 8
// speedup vs baseline: 15.9229x; 1.2576x over previous
#include <cuda_runtime.h>
#include <cuda_bf16.h>
#include <cstdint>

constexpr int Bn = 4;
constexpr int Sn = 4096;
constexpr int Dn = 256;

// Device-global scratch (no cudaMalloc allowed)
__device__ float         g_V [(size_t)Bn * Sn * Dn];   // v = xW^T+b, fp32 (epilogue/diag)
__device__ float         g_Sq[(size_t)Bn * Sn];        // per-row ||x||^2 fp32
__device__ __nv_bfloat16 g_Xb[(size_t)Bn * Sn * Dn];   // x hi (bf16)
__device__ __nv_bfloat16 g_Xl[(size_t)Bn * Sn * Dn];   // x lo (bf16 of residual)
__device__ __nv_bfloat16 g_Vb[(size_t)Bn * Sn * Dn];   // V bf16, natural layout
__device__ __nv_bfloat16 g_Wh[Dn * Dn];                // W hi
__device__ __nv_bfloat16 g_Wl[Dn * Dn];                // W lo

// ============================ helpers ============================
__device__ __forceinline__ uint32_t smem_u32(const void* p) {
    uint32_t a;
    asm("{ .reg .u64 t; cvta.to.shared.u64 t, %1; cvt.u32.u64 %0, t; }" : "=r"(a) : "l"(p));
    return a;
}
__device__ __forceinline__ void ldsm_x4(uint32_t* r, uint32_t addr) {
    asm volatile("ldmatrix.sync.aligned.m8n8.x4.shared.b16 {%0,%1,%2,%3}, [%4];"
                 : "=r"(r[0]), "=r"(r[1]), "=r"(r[2]), "=r"(r[3]) : "r"(addr));
}
__device__ __forceinline__ void ldsm_x4t(uint32_t* r, uint32_t addr) {
    asm volatile("ldmatrix.sync.aligned.m8n8.x4.trans.shared.b16 {%0,%1,%2,%3}, [%4];"
                 : "=r"(r[0]), "=r"(r[1]), "=r"(r[2]), "=r"(r[3]) : "r"(addr));
}
__device__ __forceinline__ void mma16816(float* d, const uint32_t* a, const uint32_t* b) {
    asm volatile("mma.sync.aligned.m16n8k16.row.col.f32.bf16.bf16.f32 "
                 "{%0,%1,%2,%3}, {%4,%5,%6,%7}, {%8,%9}, {%0,%1,%2,%3};"
                 : "+f"(d[0]), "+f"(d[1]), "+f"(d[2]), "+f"(d[3])
                 : "r"(a[0]), "r"(a[1]), "r"(a[2]), "r"(a[3]), "r"(b[0]), "r"(b[1]));
}
#define CP16(dst, src) \
    asm volatile("cp.async.cg.shared.global [%0], [%1], 16;" :: "r"(dst), "l"(src))
#define CP_COMMIT() asm volatile("cp.async.commit_group;" ::: "memory")
#define CP_WAIT0()  asm volatile("cp.async.wait_group 0;" ::: "memory")

__device__ __forceinline__ uint32_t pack_bf2(float a, float b) {
    __nv_bfloat162 h = __floats2bfloat162_rn(a, b);
    return *reinterpret_cast<uint32_t*>(&h);
}

// ============================ K1: x -> bf16 hi/lo + ||x||^2 ============================
__global__ void k_prep(const float* __restrict__ x) {
    int row  = blockIdx.x * 8 + (threadIdx.x >> 5);
    int lane = threadIdx.x & 31;
    const float4* p = reinterpret_cast<const float4*>(x + (size_t)row * Dn) + lane * 2;
    float4 a = p[0], b = p[1];
    float v[8] = {a.x, a.y, a.z, a.w, b.x, b.y, b.z, b.w};
    float s = 0.f;
    uint32_t hi[4], lo[4];
#pragma unroll
    for (int i = 0; i < 4; ++i) {
        float v0 = v[2 * i], v1 = v[2 * i + 1];
        s = fmaf(v0, v0, s);
        s = fmaf(v1, v1, s);
        __nv_bfloat16 h0 = __float2bfloat16(v0);
        __nv_bfloat16 h1 = __float2bfloat16(v1);
        float l0 = v0 - __bfloat162float(h0);
        float l1 = v1 - __bfloat162float(h1);
        hi[i] = pack_bf2(__bfloat162float(h0), __bfloat162float(h1));
        lo[i] = pack_bf2(l0, l1);
    }
    *reinterpret_cast<uint4*>(g_Xb + (size_t)row * Dn + lane * 8) =
        make_uint4(hi[0], hi[1], hi[2], hi[3]);
    *reinterpret_cast<uint4*>(g_Xl + (size_t)row * Dn + lane * 8) =
        make_uint4(lo[0], lo[1], lo[2], lo[3]);
#pragma unroll
    for (int of = 16; of > 0; of >>= 1) s += __shfl_xor_sync(0xffffffffu, s, of);
    if (lane == 0) g_Sq[row] = s;
}

// ============================ K1b: W -> bf16 hi/lo ============================
__global__ void k_wprep(const float* __restrict__ W) {
    int i = blockIdx.x * 256 + threadIdx.x;     // 16384 threads x 4 floats
    float4 w = reinterpret_cast<const float4*>(W)[i];
    float v[4] = {w.x, w.y, w.z, w.w};
    uint32_t hi[2], lo[2];
#pragma unroll
    for (int q = 0; q < 2; ++q) {
        __nv_bfloat16 h0 = __float2bfloat16(v[2 * q]);
        __nv_bfloat16 h1 = __float2bfloat16(v[2 * q + 1]);
        hi[q] = pack_bf2(__bfloat162float(h0), __bfloat162float(h1));
        lo[q] = pack_bf2(v[2 * q] - __bfloat162float(h0), v[2 * q + 1] - __bfloat162float(h1));
    }
    *reinterpret_cast<uint2*>(g_Wh + (size_t)i * 4) = make_uint2(hi[0], hi[1]);
    *reinterpret_cast<uint2*>(g_Wl + (size_t)i * 4) = make_uint2(lo[0], lo[1]);
}

// ============================ K2: V = xW^T + b  (HMMA, hi/lo split) ============
// CTA: 128 rows x 64 cols, 256 threads (8 warps as 4m x 2n, warp tile 32x32).
constexpr int KV_XH = 0;                        // [128][72] bf16
constexpr int KV_XL = KV_XH + 128 * 72 * 2;     // 18432
constexpr int KV_WH = KV_XL + 128 * 72 * 2;     // 36864
constexpr int KV_WL = KV_WH + 64 * 72 * 2;      // 46080
constexpr int KV_SMEM = KV_WL + 64 * 72 * 2;    // 55296

__global__ __launch_bounds__(256) void k_v2(const float* __restrict__ bv) {
    extern __shared__ char smem[];
    const uint32_t sb = smem_u32(smem);
    const int tid  = threadIdx.x;
    const int w    = tid >> 5;
    const int lane = tid & 31;
    const int lq   = lane >> 2, lr = lane & 3;
    const int r0 = blockIdx.x * 128;            // flattened row
    const int c0 = blockIdx.y * 64;             // output col
    const int m0 = (w >> 1) * 32, n0 = (w & 1) * 32;

    float acc[2][4][4] = {};

    const uint32_t aXH = sb + KV_XH + (((m0 + (lane & 15)) * 72 + ((lane >> 4) << 3)) << 1);
    const uint32_t aXL = aXH + (KV_XL - KV_XH);
    const uint32_t aWH = sb + KV_WH + (((n0 + ((lane >> 4) << 3) + (lane & 7)) * 72
                                        + (((lane >> 3) & 1) << 3)) << 1);
    const uint32_t aWL = aWH + (KV_WL - KV_WH);

    for (int kc = 0; kc < 4; ++kc) {
        __syncthreads();
        // load x hi/lo chunk [128][64] and W hi/lo chunk [64][64]
#pragma unroll
        for (int rep = 0; rep < 4; ++rep) {
            int u = tid + rep * 256;
            int r = u >> 3, cg = u & 7;
            *reinterpret_cast<uint4*>(smem + KV_XH + (r * 72 + cg * 8) * 2) =
                *reinterpret_cast<const uint4*>(g_Xb + (size_t)(r0 + r) * Dn + kc * 64 + cg * 8);
            *reinterpret_cast<uint4*>(smem + KV_XL + (r * 72 + cg * 8) * 2) =
                *reinterpret_cast<const uint4*>(g_Xl + (size_t)(r0 + r) * Dn + kc * 64 + cg * 8);
        }
#pragma unroll
        for (int rep = 0; rep < 2; ++rep) {
            int u = tid + rep * 256;
            int r = u >> 3, cg = u & 7;
            *reinterpret_cast<uint4*>(smem + KV_WH + (r * 72 + cg * 8) * 2) =
                *reinterpret_cast<const uint4*>(g_Wh + (size_t)(c0 + r) * Dn + kc * 64 + cg * 8);
            *reinterpret_cast<uint4*>(smem + KV_WL + (r * 72 + cg * 8) * 2) =
                *reinterpret_cast<const uint4*>(g_Wl + (size_t)(c0 + r) * Dn + kc * 64 + cg * 8);
        }
        __syncthreads();

#pragma unroll
        for (int ks = 0; ks < 4; ++ks) {
            const uint32_t ko = ks * 32;
            uint32_t AH[2][4], AL[2][4], BH[2][4], BL[2][4];
#pragma unroll
            for (int mt = 0; mt < 2; ++mt) {
                ldsm_x4(AH[mt], aXH + mt * (16 * 72 * 2) + ko);
                ldsm_x4(AL[mt], aXL + mt * (16 * 72 * 2) + ko);
            }
#pragma unroll
            for (int nt = 0; nt < 2; ++nt) {
                ldsm_x4(BH[nt], aWH + nt * (16 * 72 * 2) + ko);
                ldsm_x4(BL[nt], aWL + nt * (16 * 72 * 2) + ko);
            }
#pragma unroll
            for (int mt = 0; mt < 2; ++mt)
#pragma unroll
                for (int nt = 0; nt < 2; ++nt)
#pragma unroll
                    for (int nh = 0; nh < 2; ++nh) {
                        float* d = acc[mt][nt * 2 + nh];
                        mma16816(d, AH[mt], BH[nt] + nh * 2);
                        mma16816(d, AH[mt], BL[nt] + nh * 2);
                        mma16816(d, AL[mt], BH[nt] + nh * 2);
                    }
        }
    }

    // epilogue: +bias, write fp32 g_V and bf16 g_Vb
#pragma unroll
    for (int mt = 0; mt < 2; ++mt)
#pragma unroll
        for (int rr = 0; rr < 2; ++rr) {
            const int rg = r0 + m0 + mt * 16 + lq + rr * 8;
#pragma unroll
            for (int nn = 0; nn < 4; ++nn) {
                const int cg = c0 + n0 + nn * 8 + 2 * lr;
                float v0 = acc[mt][nn][rr * 2 + 0] + bv[cg];
                float v1 = acc[mt][nn][rr * 2 + 1] + bv[cg + 1];
                *reinterpret_cast<float2*>(g_V + (size_t)rg * Dn + cg) = make_float2(v0, v1);
                *reinterpret_cast<uint32_t*>(g_Vb + (size_t)rg * Dn + cg) = pack_bf2(v0, v1);
            }
        }
}

// ============================ K3: fused HMMA main kernel ====================
// smem strides: stride mod 128B == 16B -> conflict-free ldmatrix
constexpr int XS_STR = 264;   // [128] rows
constexpr int XT_STR = 264;   // [64] rows, 2 buffers
constexpr int VB_STR = 264;   // [64] rows natural [t][d], 2 buffers
constexpr int P_STR  = 72;    // [128] rows

constexpr int OFF_RS = 0;                              // 512
constexpr int OFF_P  = 512;                            // 18432 -> 18944
constexpr int OFF_XS = 18944;                          // 67584 -> 86528
constexpr int OFF_XT = 86528;                          // 2 x 33792 -> 154112
constexpr int OFF_VB = 154112;                         // 2 x 33792 -> 221696
constexpr int XT_BUF = 64 * XT_STR * 2;                // 33792
constexpr int SMEM_MAIN = 221696;

__global__ __launch_bounds__(512, 1) void k_main(const float* __restrict__ logt,
                                                 float* __restrict__ out) {
    extern __shared__ char smem[];
    const uint32_t sb = smem_u32(smem);
    float* s_rs = reinterpret_cast<float*>(smem + OFF_RS);

    const int tid  = threadIdx.x;
    const int w    = tid >> 5;
    const int lane = tid & 31;
    const int lq   = lane >> 2, lr = lane & 3;

    const int bz = blockIdx.y;
    const int s0 = blockIdx.x * 128;
    const size_t base = (size_t)bz * Sn * Dn;
    const size_t bzS  = (size_t)bz * Sn;

    // phase-1 warp tile 16x32 (warps 8x2); phase-2 warp tile 32x64 (warps 4x4)
    const int m0  = (w >> 1) * 16, n0  = (w & 1) * 32;
    const int m0b = (w >> 2) * 32, n0b = (w & 3) * 64;

    if (tid < 128) s_rs[tid] = 0.f;

    // ---- prologue: async loads of XS + tile 0 ----
#pragma unroll
    for (int rep = 0; rep < 8; ++rep) {
        int u = tid + rep * 512;
        int r = u >> 5, cg = u & 31;
        CP16(sb + OFF_XS + (r * XS_STR + cg * 8) * 2,
             g_Xb + base + (size_t)(s0 + r) * Dn + cg * 8);
    }
#pragma unroll
    for (int rep = 0; rep < 4; ++rep) {
        int u = tid + rep * 512;
        int r = u >> 5, cg = u & 31;
        CP16(sb + OFF_XT + (r * XT_STR + cg * 8) * 2,
             g_Xb + base + (size_t)r * Dn + cg * 8);
        CP16(sb + OFF_VB + (r * VB_STR + cg * 8) * 2,
             g_Vb + base + (size_t)r * Dn + cg * 8);
    }
    CP_COMMIT();

    const float temp  = fmaxf(expf(logt[0]), 1e-5f);
    const float invT2 = __fdividef(1.f, temp * temp);

    const int ra = m0 + lq, rb = ra + 8;       // phase-1 rows owned by this lane
    const float sqA = g_Sq[bzS + s0 + ra];
    const float sqB = g_Sq[bzS + s0 + rb];

    // ldmatrix per-lane base addresses
    const uint32_t aA  = sb + OFF_XS + (((m0 + (lane & 15)) * XS_STR + ((lane >> 4) << 3)) << 1);
    const uint32_t aB0 = sb + OFF_XT + (((n0 + ((lane >> 4) << 3) + (lane & 7)) * XT_STR
                                         + (((lane >> 3) & 1) << 3)) << 1);
    const uint32_t aB1 = aB0 + 16 * XT_STR * 2;
    const uint32_t aP0 = sb + OFF_P + (((m0b + (lane & 15)) * P_STR + ((lane >> 4) << 3)) << 1);
    const uint32_t aP1 = aP0 + 16 * P_STR * 2;
    // phase-2 B: trans ldsm on VB natural [t][d]; bit3 -> t-half, bit4 -> d-half
    const uint32_t aVb = sb + OFF_VB + (((((lane >> 3) & 1) * 8 + (lane & 7)) * VB_STR
                                          + n0b + ((lane >> 4) << 3)) << 1);

    float dacc[2][8][4];
#pragma unroll
    for (int a = 0; a < 2; ++a)
#pragma unroll
        for (int b = 0; b < 8; ++b)
#pragma unroll
            for (int c = 0; c < 4; ++c) dacc[a][b][c] = 0.f;
    float rsA = 0.f, rsB = 0.f;

    for (int jt = 0; jt < 64; ++jt) {
        const int t0 = jt * 64;
        const uint32_t bo = (uint32_t)(jt & 1) * XT_BUF;

        CP_WAIT0();
        __syncthreads();

        // ---- prefetch next tile into the other buffer ----
        if (jt < 63) {
            const uint32_t bn = bo ^ XT_BUF;
            const int tn = t0 + 64;
#pragma unroll
            for (int rep = 0; rep < 4; ++rep) {
                int u = tid + rep * 512;
                int r = u >> 5, cg = u & 31;
                CP16(sb + OFF_XT + bn + (r * XT_STR + cg * 8) * 2,
                     g_Xb + base + (size_t)(tn + r) * Dn + cg * 8);
                CP16(sb + OFF_VB + bn + (r * VB_STR + cg * 8) * 2,
                     g_Vb + base + (size_t)(tn + r) * Dn + cg * 8);
            }
        }
        CP_COMMIT();

        // ---- prefetch per-iter ||x_t||^2 (consumed after phase 1) ----
        float2 t4[4];
#pragma unroll
        for (int fn = 0; fn < 4; ++fn)
            t4[fn] = *reinterpret_cast<const float2*>(g_Sq + bzS + t0 + n0 + fn * 8 + 2 * lr);

        // ---- phase 1: S = Xs @ Xt^T  (16x32 per warp, K=256) ----
        float sacc[4][4];
#pragma unroll
        for (int f = 0; f < 4; ++f)
#pragma unroll
            for (int c = 0; c < 4; ++c) sacc[f][c] = 0.f;
        {
            uint32_t pa = aA, pb0 = aB0 + bo, pb1 = aB1 + bo;
#pragma unroll
            for (int ks = 0; ks < 16; ++ks) {
                uint32_t A[4], B0[4], B1[4];
                ldsm_x4(A, pa);
                ldsm_x4(B0, pb0);
                ldsm_x4(B1, pb1);
                mma16816(sacc[0], A, B0);
                mma16816(sacc[1], A, B0 + 2);
                mma16816(sacc[2], A, B1);
                mma16816(sacc[3], A, B1 + 2);
                pa += 32; pb0 += 32; pb1 += 32;
            }
        }

        // ---- elementwise: Cauchy, diag-zero, rowsum, bf16 pack -> P ----
#pragma unroll
        for (int fn = 0; fn < 4; ++fn) {
            const int c = n0 + fn * 8 + 2 * lr;
            const float sqt0 = t4[fn].x;
            const float sqt1 = t4[fn].y;
            float d00 = fmaxf(sqA + sqt0 - 2.f * sacc[fn][0], 0.f);
            float d01 = fmaxf(sqA + sqt1 - 2.f * sacc[fn][1], 0.f);
            float d10 = fmaxf(sqB + sqt0 - 2.f * sacc[fn][2], 0.f);
            float d11 = fmaxf(sqB + sqt1 - 2.f * sacc[fn][3], 0.f);
            float k00 = __fdividef(1.f, fmaf(d00, invT2, 1.f));
            float k01 = __fdividef(1.f, fmaf(d01, invT2, 1.f));
            float k10 = __fdividef(1.f, fmaf(d10, invT2, 1.f));
            float k11 = __fdividef(1.f, fmaf(d11, invT2, 1.f));
            if (s0 + ra == t0 + c)     k00 = 0.f;
            if (s0 + ra == t0 + c + 1) k01 = 0.f;
            if (s0 + rb == t0 + c)     k10 = 0.f;
            if (s0 + rb == t0 + c + 1) k11 = 0.f;
            rsA += k00 + k01;
            rsB += k10 + k11;
            *reinterpret_cast<uint32_t*>(smem + OFF_P + (ra * P_STR + c) * 2) = pack_bf2(k00, k01);
            *reinterpret_cast<uint32_t*>(smem + OFF_P + (rb * P_STR + c) * 2) = pack_bf2(k10, k11);
        }
        __syncthreads();

        // ---- phase 2: D += P @ V  (32x64 per warp, K=64, trans-ldsm B) ----
        {
            uint32_t qa0 = aP0, qa1 = aP1;
            uint32_t qv = aVb + bo;
#pragma unroll
            for (int ks = 0; ks < 4; ++ks) {
                uint32_t A0[4], A1[4], Bv[4][4];
                ldsm_x4(A0, qa0);
                ldsm_x4(A1, qa1);
#pragma unroll
                for (int q = 0; q < 4; ++q) ldsm_x4t(Bv[q], qv + q * 32);
#pragma unroll
                for (int q = 0; q < 4; ++q) {
                    mma16816(dacc[0][q * 2 + 0], A0, Bv[q]);
                    mma16816(dacc[1][q * 2 + 0], A1, Bv[q]);
                    mma16816(dacc[0][q * 2 + 1], A0, Bv[q] + 2);
                    mma16816(dacc[1][q * 2 + 1], A1, Bv[q] + 2);
                }
                qa0 += 32; qa1 += 32;
                qv += 16 * VB_STR * 2;
            }
        }
    }

    // ---- rowsum reduce ----
    __syncthreads();
    atomicAdd(&s_rs[ra], rsA);
    atomicAdd(&s_rs[rb], rsB);
    __syncthreads();

    // ---- epilogue: out = (D + v_row) / (rowsum + 1) ----
#pragma unroll
    for (int mi = 0; mi < 2; ++mi) {
        const int r0e = m0b + mi * 16 + lq;
        const int r1e = r0e + 8;
        const float invA = __fdividef(1.f, s_rs[r0e] + 1.f);
        const float invB = __fdividef(1.f, s_rs[r1e] + 1.f);
        const size_t go0 = (bzS + s0 + r0e) * Dn;
        const size_t go1 = (bzS + s0 + r1e) * Dn;
#pragma unroll
        for (int fn = 0; fn < 8; ++fn) {
            const int c = n0b + fn * 8 + 2 * lr;
            float2 v0 = *reinterpret_cast<const float2*>(g_V + go0 + c);
            float2 v1 = *reinterpret_cast<const float2*>(g_V + go1 + c);
            float2 o0, o1;
            o0.x = (dacc[mi][fn][0] + v0.x) * invA;
            o0.y = (dacc[mi][fn][1] + v0.y) * invA;
            o1.x = (dacc[mi][fn][2] + v1.x) * invB;
            o1.y = (dacc[mi][fn][3] + v1.y) * invB;
            *reinterpret_cast<float2*>(out + go0 + c) = o0;
            *reinterpret_cast<float2*>(out + go1 + c) = o1;
        }
    }
}

// ============================ launch ============================
extern "C" void kernel_launch(void* const* d_in, const int* in_sizes, int n_in,
                              void* d_out, int out_size) {
    const float* x    = (const float*)d_in[0];
    const float* W    = (const float*)d_in[1];
    const float* bv   = (const float*)d_in[2];
    const float* logt = (const float*)d_in[3];
    float* out = (float*)d_out;

    cudaFuncSetAttribute(k_v2,   cudaFuncAttributeMaxDynamicSharedMemorySize, KV_SMEM);
    cudaFuncSetAttribute(k_main, cudaFuncAttributeMaxDynamicSharedMemorySize, SMEM_MAIN);

    k_prep<<<(Bn * Sn) / 8, 256>>>(x);
    k_wprep<<<64, 256>>>(W);
    k_v2<<<dim3((Bn * Sn) / 128, Dn / 64), 256, KV_SMEM>>>(bv);
    k_main<<<dim3(Sn / 128, Bn), 512, SMEM_MAIN>>>(logt, out);
}